// round 1
// baseline (speedup 1.0000x reference)
#include <cuda_runtime.h>
#include <math.h>

#define L_    13
#define B_    16
#define S_    512
#define H_    768
#define QL    20
#define DL    492          // S_ - QL
#define NB    11
#define HID   5
#define NALL  14           // L_ + 1 (layer 0 duplicated)
#define KC    64           // H chunk per smem stage
#define DC    128          // d-columns per CTA
#define NDCH  4            // ceil(DL / DC)
#define EPSF  1e-8f
#define THR   128

// Persistent scratch: integer histogram counts per (layer, batch, bin).
__device__ int g_hist[L_ * B_ * NB];

__global__ void zero_hist_kernel() {
    int i = blockIdx.x * blockDim.x + threadIdx.x;
    if (i < L_ * B_ * NB) g_hist[i] = 0;
}

// One CTA: layer l, batch b, d-columns [dc*128, dc*128+128).
// Computes 20 x 128 cosine-sim tile + local histogram, accumulates to g_hist.
__global__ __launch_bounds__(THR) void simhist_kernel(const float* __restrict__ hs) {
    __shared__ float sQ[QL][KC + 4];    // +4 pad: float4-aligned, bank-safe
    __shared__ float sD[DC][KC + 4];
    __shared__ float sQn[QL];
    __shared__ float sDn[DC];
    __shared__ int   sHist[NB];

    const int dc = blockIdx.x, b = blockIdx.y, l = blockIdx.z;
    const int tid  = threadIdx.x;
    const int lane = tid & 31;
    const int qg   = tid >> 5;          // 0..3: q-row group (5 rows each)
    const int dstart = dc * DC;

    const float* base = hs + (size_t)(l * B_ + b) * S_ * H_;

    float acc[5][4];
    #pragma unroll
    for (int j = 0; j < 5; j++)
        #pragma unroll
        for (int c = 0; c < 4; c++) acc[j][c] = 0.f;

    float dn2 = 0.f;                    // this thread owns column lane + 32*qg
    float qn2 = 0.f;                    // warp 1 lanes 0..19 own q-row = lane

    if (tid < NB) sHist[tid] = 0;

    for (int h0 = 0; h0 < H_; h0 += KC) {
        // ---- stage Q tile: 20 rows x 64 cols (320 float4, coalesced) ----
        for (int i = tid; i < QL * (KC / 4); i += THR) {
            int qi = i >> 4, k4 = i & 15;
            float4 v = *reinterpret_cast<const float4*>(base + (size_t)qi * H_ + h0 + k4 * 4);
            *reinterpret_cast<float4*>(&sQ[qi][k4 * 4]) = v;
        }
        // ---- stage D tile: 128 rows x 64 cols (2048 float4, coalesced) ----
        for (int i = tid; i < DC * (KC / 4); i += THR) {
            int dr = i >> 4, k4 = i & 15;
            int dgl = dstart + dr;
            float4 v = make_float4(0.f, 0.f, 0.f, 0.f);
            if (dgl < DL)
                v = *reinterpret_cast<const float4*>(base + (size_t)(QL + dgl) * H_ + h0 + k4 * 4);
            *reinterpret_cast<float4*>(&sD[dr][k4 * 4]) = v;
        }
        __syncthreads();

        // q-norms: warp 1, lanes 0..19 (bank-stride 68 -> conflict-free)
        if (qg == 1 && lane < QL) {
            #pragma unroll 8
            for (int k = 0; k < KC; k++) { float q = sQ[lane][k]; qn2 += q * q; }
        }

        // ---- main FMA loop: per k4: 9 LDS.128, 80+4 FMA ----
        #pragma unroll 4
        for (int k4 = 0; k4 < KC / 4; k4++) {
            float4 dv[4], qv[5];
            #pragma unroll
            for (int c = 0; c < 4; c++)
                dv[c] = *reinterpret_cast<const float4*>(&sD[lane + 32 * c][k4 * 4]);
            #pragma unroll
            for (int j = 0; j < 5; j++)
                qv[j] = *reinterpret_cast<const float4*>(&sQ[qg * 5 + j][k4 * 4]);
            #pragma unroll
            for (int j = 0; j < 5; j++)
                #pragma unroll
                for (int c = 0; c < 4; c++) {
                    acc[j][c] += qv[j].x * dv[c].x;
                    acc[j][c] += qv[j].y * dv[c].y;
                    acc[j][c] += qv[j].z * dv[c].z;
                    acc[j][c] += qv[j].w * dv[c].w;
                }
            // d-norm for this thread's owned column (c == qg): evenly spread
            {
                float4 dq = dv[qg];
                dn2 += dq.x * dq.x + dq.y * dq.y + dq.z * dq.z + dq.w * dq.w;
            }
        }
        __syncthreads();
    }

    // ---- epilogue: norms -> sim -> bin -> warp-aggregated histogram ----
    sDn[lane + 32 * qg] = sqrtf(dn2);
    if (qg == 1 && lane < QL) sQn[lane] = sqrtf(qn2);
    __syncthreads();

    #pragma unroll
    for (int j = 0; j < 5; j++) {
        float qn = sQn[qg * 5 + j];
        #pragma unroll
        for (int c = 0; c < 4; c++) {
            int col = lane + 32 * c;
            int idx = -1;
            if (dstart + col < DL) {
                float sim = acc[j][c] / fmaxf(qn * sDn[col], EPSF);
                float t = (sim + 1.0f) * 5.5f;   // bin width = 2/11
                int bi = (int)floorf(t);
                if (bi >= 0 && bi < NB) idx = bi;
            }
            // warp-aggregate: lanes with same bin -> single atomic
            unsigned m = __match_any_sync(0xffffffffu, idx);
            if (idx >= 0) {
                int leader = __ffs(m) - 1;
                if (lane == leader) atomicAdd(&sHist[idx], __popc(m));
            }
        }
    }
    __syncthreads();
    if (tid < NB) atomicAdd(&g_hist[(l * B_ + b) * NB + tid], sHist[tid]);
}

// Final: out[b] = cls . W_comb[:768] + sum_{l',o} hfeat * W_comb[768+...] + consts
__global__ void final_kernel(const float* __restrict__ hs,
                             const float* __restrict__ W_hist,
                             const float* __restrict__ b_hist,
                             const float* __restrict__ W_comb,
                             const float* __restrict__ b_comb,
                             float* __restrict__ out) {
    const int b = blockIdx.x;
    const int tid = threadIdx.x;
    __shared__ float red[256];

    float sum = 0.f;
    // cls = hidden_states[12][b][0][:]
    const float* cls = hs + (size_t)(12 * B_ + b) * S_ * H_;
    for (int h = tid; h < H_; h += 256) sum += cls[h] * W_comb[h];

    // histogram features: 14 all-layers x 11 bins; layer 0 used twice
    const float inv_n = 1.0f / (float)(QL * DL);
    for (int i = tid; i < NALL * NB; i += 256) {
        int lp = i / NB, n = i % NB;
        int lsrc = (lp == 0) ? 0 : lp - 1;
        float hv = (float)g_hist[(lsrc * B_ + b) * NB + n] * inv_n;
        float coef = 0.f;
        #pragma unroll
        for (int o = 0; o < HID; o++)
            coef += W_hist[o * NB + n] * W_comb[H_ + lp * HID + o];
        sum += hv * coef;
    }
    if (tid == 0) {
        float cst = b_comb[0];
        for (int lp = 0; lp < NALL; lp++)
            #pragma unroll
            for (int o = 0; o < HID; o++)
                cst += b_hist[o] * W_comb[H_ + lp * HID + o];
        sum += cst;
    }

    red[tid] = sum;
    __syncthreads();
    for (int s = 128; s > 0; s >>= 1) {
        if (tid < s) red[tid] += red[tid + s];
        __syncthreads();
    }
    if (tid == 0) out[b] = red[0];
}

extern "C" void kernel_launch(void* const* d_in, const int* in_sizes, int n_in,
                              void* d_out, int out_size) {
    const float* hs     = (const float*)d_in[0];
    const float* W_hist = (const float*)d_in[1];
    const float* b_hist = (const float*)d_in[2];
    const float* W_comb = (const float*)d_in[3];
    const float* b_comb = (const float*)d_in[4];
    float* out = (float*)d_out;

    zero_hist_kernel<<<(L_ * B_ * NB + 255) / 256, 256>>>();
    dim3 grid(NDCH, B_, L_);
    simhist_kernel<<<grid, THR>>>(hs);
    final_kernel<<<B_, 256>>>(hs, W_hist, b_hist, W_comb, b_comb, out);
}

// round 2
// speedup vs baseline: 1.0597x; 1.0597x over previous
#include <cuda_runtime.h>
#include <math.h>

#define L_    13
#define B_    16
#define S_    512
#define H_    768
#define QL    20
#define DL    492          // S_ - QL
#define NB    11
#define HID   5
#define NALL  14           // L_ + 1 (layer 0 duplicated)
#define KC    64           // H chunk per smem stage (16 float4)
#define K4N   16           // KC / 4
#define DC    128          // d-columns per CTA
#define NDCH  4            // ceil(DL / DC)
#define EPSF  1e-8f
#define THR   128

// Per-(l,b,dc) private histogram partials: no zeroing, no global atomics.
__device__ int g_hist[L_ * B_ * NDCH * NB];

// ---- packed f32x2 helpers (Blackwell FFMA2: 2x fp32 FLOP per issue) ----
__device__ __forceinline__ void ffma2(unsigned long long& d,
                                      unsigned long long a,
                                      unsigned long long b) {
    asm("fma.rn.f32x2 %0, %1, %2, %0;" : "+l"(d) : "l"(a), "l"(b));
}
__device__ __forceinline__ float2 unpack2(unsigned long long v) {
    float2 r;
    asm("mov.b64 {%0,%1}, %2;" : "=f"(r.x), "=f"(r.y) : "l"(v));
    return r;
}

// One CTA: layer l, batch b, d-columns [dc*128, dc*128+128).
__global__ __launch_bounds__(THR) void simhist_kernel(const float* __restrict__ hs) {
    __shared__ float4 sQ4[K4N][QL];        // [k4][q]   (reads are broadcast)
    __shared__ float4 sD4[K4N][DC];        // [k4][d^swz] XOR-swizzled
    __shared__ float  sQn[QL];
    __shared__ float  sDn[DC];
    __shared__ int    sHist[NB];

    const int dc = blockIdx.x, b = blockIdx.y, l = blockIdx.z;
    const int tid  = threadIdx.x;
    const int lane = tid & 31;
    const int qg   = tid >> 5;             // warp id: 5 q-rows each
    const int dstart = dc * DC;

    const float* base = hs + (size_t)(l * B_ + b) * S_ * H_;

    unsigned long long acc[5][4];
    #pragma unroll
    for (int j = 0; j < 5; j++)
        #pragma unroll
        for (int c = 0; c < 4; c++) acc[j][c] = 0ULL;

    unsigned long long dn2p = 0ULL;        // owns column lane + 32*qg
    unsigned long long qn2p = 0ULL;        // threads 0..19 own q-row = tid

    if (tid < NB) sHist[tid] = 0;

    for (int h0 = 0; h0 < H_; h0 += KC) {
        // ---- stage Q: 320 float4; i -> (qi = i>>4, k4 = i&15) coalesced ----
        for (int i = tid; i < QL * K4N; i += THR) {
            int qi = i >> 4, k4 = i & 15;
            sQ4[k4][qi] = *reinterpret_cast<const float4*>(
                base + (size_t)qi * H_ + h0 + k4 * 4);
        }
        // ---- stage D: 2048 float4; i -> (dr = i>>4, k4 = i&15) coalesced ----
        for (int i = tid; i < DC * K4N; i += THR) {
            int dr = i >> 4, k4 = i & 15;
            int dgl = dstart + dr;
            float4 v = make_float4(0.f, 0.f, 0.f, 0.f);
            if (dgl < DL)
                v = *reinterpret_cast<const float4*>(
                    base + (size_t)(QL + dgl) * H_ + h0 + k4 * 4);
            sD4[k4][dr ^ (k4 & 7)] = v;    // XOR swizzle: 4 lanes/bank-group
        }
        __syncthreads();

        // q-norms: threads 0..19 (lane-stride-16B LDS.128, conflict-free)
        if (tid < QL) {
            #pragma unroll
            for (int k4 = 0; k4 < K4N; k4++) {
                ulonglong2 qq = *reinterpret_cast<const ulonglong2*>(&sQ4[k4][tid]);
                ffma2(qn2p, qq.x, qq.x);
                ffma2(qn2p, qq.y, qq.y);
            }
        }

        // ---- main loop: per k4: 9 LDS.128 + 42 FFMA2 per thread ----
        #pragma unroll 4
        for (int k4 = 0; k4 < K4N; k4++) {
            const int swz = k4 & 7;
            ulonglong2 dv[4], qv[5];
            #pragma unroll
            for (int c = 0; c < 4; c++)
                dv[c] = *reinterpret_cast<const ulonglong2*>(
                    &sD4[k4][(lane + 32 * c) ^ swz]);
            #pragma unroll
            for (int j = 0; j < 5; j++)
                qv[j] = *reinterpret_cast<const ulonglong2*>(&sQ4[k4][qg * 5 + j]);
            #pragma unroll
            for (int j = 0; j < 5; j++)
                #pragma unroll
                for (int c = 0; c < 4; c++) {
                    ffma2(acc[j][c], qv[j].x, dv[c].x);
                    ffma2(acc[j][c], qv[j].y, dv[c].y);
                }
            // d-norm for owned column (c == qg)
            ffma2(dn2p, dv[qg].x, dv[qg].x);
            ffma2(dn2p, dv[qg].y, dv[qg].y);
        }
        __syncthreads();
    }

    // ---- epilogue: norms -> sim -> bin -> warp-aggregated histogram ----
    {
        float2 d2 = unpack2(dn2p);
        sDn[lane + 32 * qg] = sqrtf(d2.x + d2.y);
    }
    if (tid < QL) {
        float2 q2 = unpack2(qn2p);
        sQn[tid] = sqrtf(q2.x + q2.y);
    }
    __syncthreads();

    #pragma unroll
    for (int j = 0; j < 5; j++) {
        float qn = sQn[qg * 5 + j];
        #pragma unroll
        for (int c = 0; c < 4; c++) {
            int col = lane + 32 * c;
            int idx = -1;
            if (dstart + col < DL) {
                float2 a2 = unpack2(acc[j][c]);
                float sim = (a2.x + a2.y) / fmaxf(qn * sDn[col], EPSF);
                float t = (sim + 1.0f) * 5.5f;   // bin width = 2/11
                int bi = (int)floorf(t);
                if (bi >= 0 && bi < NB) idx = bi;
            }
            unsigned m = __match_any_sync(0xffffffffu, idx);
            if (idx >= 0 && lane == (__ffs(m) - 1))
                atomicAdd(&sHist[idx], __popc(m));
        }
    }
    __syncthreads();
    if (tid < NB)
        g_hist[((l * B_ + b) * NDCH + dc) * NB + tid] = sHist[tid];  // private slot
}

// out[b] = cls . W_comb[:768] + sum hfeat * W_comb[768+...] + consts
__global__ void final_kernel(const float* __restrict__ hs,
                             const float* __restrict__ W_hist,
                             const float* __restrict__ b_hist,
                             const float* __restrict__ W_comb,
                             const float* __restrict__ b_comb,
                             float* __restrict__ out) {
    const int b = blockIdx.x;
    const int tid = threadIdx.x;
    __shared__ float red[256];

    float sum = 0.f;
    const float* cls = hs + (size_t)(12 * B_ + b) * S_ * H_;   // layer 12, seq 0
    for (int h = tid; h < H_; h += 256) sum += cls[h] * W_comb[h];

    const float inv_n = 1.0f / (float)(QL * DL);
    for (int i = tid; i < NALL * NB; i += 256) {
        int lp = i / NB, n = i % NB;
        int lsrc = (lp == 0) ? 0 : lp - 1;
        int cnt = 0;
        #pragma unroll
        for (int d = 0; d < NDCH; d++)
            cnt += g_hist[((lsrc * B_ + b) * NDCH + d) * NB + n];
        float hv = (float)cnt * inv_n;
        float coef = 0.f;
        #pragma unroll
        for (int o = 0; o < HID; o++)
            coef += W_hist[o * NB + n] * W_comb[H_ + lp * HID + o];
        sum += hv * coef;
    }
    if (tid == 0) {
        float cst = b_comb[0];
        for (int lp = 0; lp < NALL; lp++)
            #pragma unroll
            for (int o = 0; o < HID; o++)
                cst += b_hist[o] * W_comb[H_ + lp * HID + o];
        sum += cst;
    }

    red[tid] = sum;
    __syncthreads();
    for (int s = 128; s > 0; s >>= 1) {
        if (tid < s) red[tid] += red[tid + s];
        __syncthreads();
    }
    if (tid == 0) out[b] = red[0];
}

extern "C" void kernel_launch(void* const* d_in, const int* in_sizes, int n_in,
                              void* d_out, int out_size) {
    const float* hs     = (const float*)d_in[0];
    const float* W_hist = (const float*)d_in[1];
    const float* b_hist = (const float*)d_in[2];
    const float* W_comb = (const float*)d_in[3];
    const float* b_comb = (const float*)d_in[4];
    float* out = (float*)d_out;

    dim3 grid(NDCH, B_, L_);
    simhist_kernel<<<grid, THR>>>(hs);
    final_kernel<<<B_, 256>>>(hs, W_hist, b_hist, W_comb, b_comb, out);
}

// round 3
// speedup vs baseline: 1.1000x; 1.0379x over previous
#include <cuda_runtime.h>
#include <math.h>

#define L_    13
#define B_    16
#define S_    512
#define H_    768
#define QL    20
#define DL    492          // S_ - QL
#define NB    11
#define HID   5
#define NALL  14           // L_ + 1 (layer 0 duplicated)
#define KC    32           // H chunk per stage (8 float4)
#define K4N   8            // KC / 4
#define NCH   24           // H_ / KC
#define DC    128          // d-columns per CTA
#define NDCH  4            // ceil(DL / DC)
#define QSTR  21           // padded Q row stride (bank-spread for staging)
#define EPSF  1e-8f
#define THR   256

// Per-(l,b,dc) private histogram partials: no zeroing, no global atomics.
__device__ int g_hist[L_ * B_ * NDCH * NB];

// ---- packed f32x2 FFMA2 helpers ----
__device__ __forceinline__ void ffma2(unsigned long long& d,
                                      unsigned long long a,
                                      unsigned long long b) {
    asm("fma.rn.f32x2 %0, %1, %2, %0;" : "+l"(d) : "l"(a), "l"(b));
}
__device__ __forceinline__ float2 unpack2(unsigned long long v) {
    float2 r;
    asm("mov.b64 {%0,%1}, %2;" : "=f"(r.x), "=f"(r.y) : "l"(v));
    return r;
}

// ---- cp.async 16B with zero-fill predicate ----
__device__ __forceinline__ void cp16(void* dst, const void* src, bool pred) {
    unsigned s = (unsigned)__cvta_generic_to_shared(dst);
    int n = pred ? 16 : 0;
    asm volatile("cp.async.cg.shared.global [%0], [%1], 16, %2;"
                 :: "r"(s), "l"(src), "r"(n));
}
__device__ __forceinline__ void cp_commit() {
    asm volatile("cp.async.commit_group;");
}
template <int N>
__device__ __forceinline__ void cp_wait() {
    asm volatile("cp.async.wait_group %0;" :: "n"(N));
}

__global__ void nop_kernel() {}

// One CTA: layer l, batch b, d-columns [dc*128, dc*128+128).
// 256 threads: warp w -> q-group (w>>1)*5, d-half (w&1)*64; thread: 5q x 2d.
__global__ __launch_bounds__(THR, 2) void simhist_kernel(const float* __restrict__ hs) {
    __shared__ float4 sQ4[2][K4N][QSTR];   // [buf][k4][q]
    __shared__ float4 sD4[2][K4N][DC];     // [buf][k4][d ^ k4]
    __shared__ float  sQn[QL];
    __shared__ float  sDn[DC];
    __shared__ int    sHist[NB];

    const int dc = blockIdx.x, b = blockIdx.y, l = blockIdx.z;
    const int tid  = threadIdx.x;
    const int lane = tid & 31;
    const int wid  = tid >> 5;
    const int qg   = wid >> 1;             // 0..3: q rows [5qg, 5qg+5)
    const int dh   = wid & 1;              // d-half: cols 64*dh + ...
    const int dstart = dc * DC;

    const float* base = hs + (size_t)(l * B_ + b) * S_ * H_;
    const float* dbase = base + (size_t)QL * H_;

    unsigned long long acc[5][2];
    #pragma unroll
    for (int j = 0; j < 5; j++) { acc[j][0] = 0ULL; acc[j][1] = 0ULL; }
    unsigned long long dn2p = 0ULL;        // qg<2: owns col 64*dh + 32*qg + lane
    unsigned long long qn2p = 0ULL;        // tid<20: owns q-row tid

    if (tid < NB) sHist[tid] = 0;

    // ---- stage loader: chunk c into buffer s ----
    auto load_chunk = [&](int c, int s) {
        int h0 = c * KC;
        // Q: 160 float4 (threads 0..159)
        if (tid < QL * K4N) {
            int qi = tid >> 3, k4 = tid & 7;
            cp16(&sQ4[s][k4][qi], base + (size_t)qi * H_ + h0 + k4 * 4, true);
        }
        // D: 1024 float4, 4 per thread
        #pragma unroll
        for (int t = 0; t < 4; t++) {
            int i = tid + t * THR;
            int dr = i >> 3, k4 = i & 7;
            int dgl = dstart + dr;
            cp16(&sD4[s][k4][dr ^ k4],
                 dbase + (size_t)dgl * H_ + h0 + k4 * 4, dgl < DL);
        }
        cp_commit();
    };

    load_chunk(0, 0);

    for (int c = 0; c < NCH; c++) {
        const int s = c & 1;
        if (c + 1 < NCH) { load_chunk(c + 1, s ^ 1); cp_wait<1>(); }
        else            { cp_wait<0>(); }
        __syncthreads();

        // q-norms: threads 0..19 (stride-16B LDS.128, conflict-free)
        if (tid < QL) {
            #pragma unroll
            for (int k4 = 0; k4 < K4N; k4++) {
                ulonglong2 qq = *reinterpret_cast<const ulonglong2*>(&sQ4[s][k4][tid]);
                ffma2(qn2p, qq.x, qq.x);
                ffma2(qn2p, qq.y, qq.y);
            }
        }

        // main loop: per k4: 7 LDS.128 + ~21 FFMA2 per thread
        #pragma unroll 2
        for (int k4 = 0; k4 < K4N; k4++) {
            ulonglong2 dv[2], qv[5];
            #pragma unroll
            for (int cix = 0; cix < 2; cix++)
                dv[cix] = *reinterpret_cast<const ulonglong2*>(
                    &sD4[s][k4][(64 * dh + 32 * cix + lane) ^ k4]);
            #pragma unroll
            for (int j = 0; j < 5; j++)
                qv[j] = *reinterpret_cast<const ulonglong2*>(&sQ4[s][k4][qg * 5 + j]);
            #pragma unroll
            for (int j = 0; j < 5; j++) {
                ffma2(acc[j][0], qv[j].x, dv[0].x);
                ffma2(acc[j][0], qv[j].y, dv[0].y);
                ffma2(acc[j][1], qv[j].x, dv[1].x);
                ffma2(acc[j][1], qv[j].y, dv[1].y);
            }
            if (qg < 2) {                    // d-norm for owned column
                ffma2(dn2p, dv[qg].x, dv[qg].x);
                ffma2(dn2p, dv[qg].y, dv[qg].y);
            }
        }
        __syncthreads();   // buffer s free for reuse by load(c+2)
    }

    // ---- epilogue ----
    if (qg < 2) {
        float2 d2 = unpack2(dn2p);
        sDn[64 * dh + 32 * qg + lane] = sqrtf(d2.x + d2.y);
    }
    if (tid < QL) {
        float2 q2 = unpack2(qn2p);
        sQn[tid] = sqrtf(q2.x + q2.y);
    }
    __syncthreads();

    #pragma unroll
    for (int j = 0; j < 5; j++) {
        float qn = sQn[qg * 5 + j];
        #pragma unroll
        for (int cix = 0; cix < 2; cix++) {
            int col = 64 * dh + 32 * cix + lane;
            int idx = -1;
            if (dstart + col < DL) {
                float2 a2 = unpack2(acc[j][cix]);
                float sim = (a2.x + a2.y) / fmaxf(qn * sDn[col], EPSF);
                float t = (sim + 1.0f) * 5.5f;   // bin width = 2/11
                int bi = (int)floorf(t);
                if (bi >= 0 && bi < NB) idx = bi;
            }
            unsigned m = __match_any_sync(0xffffffffu, idx);
            if (idx >= 0 && lane == (__ffs(m) - 1))
                atomicAdd(&sHist[idx], __popc(m));
        }
    }
    __syncthreads();
    if (tid < NB)
        g_hist[((l * B_ + b) * NDCH + dc) * NB + tid] = sHist[tid];
}

// out[b] = cls . W_comb[:768] + sum hfeat * W_comb[768+...] + consts
__global__ void final_kernel(const float* __restrict__ hs,
                             const float* __restrict__ W_hist,
                             const float* __restrict__ b_hist,
                             const float* __restrict__ W_comb,
                             const float* __restrict__ b_comb,
                             float* __restrict__ out) {
    const int b = blockIdx.x;
    const int tid = threadIdx.x;
    __shared__ float red[256];

    float sum = 0.f;
    const float* cls = hs + (size_t)(12 * B_ + b) * S_ * H_;   // layer 12, seq 0
    for (int h = tid; h < H_; h += 256) sum += cls[h] * W_comb[h];

    const float inv_n = 1.0f / (float)(QL * DL);
    for (int i = tid; i < NALL * NB; i += 256) {
        int lp = i / NB, n = i % NB;
        int lsrc = (lp == 0) ? 0 : lp - 1;
        int cnt = 0;
        #pragma unroll
        for (int d = 0; d < NDCH; d++)
            cnt += g_hist[((lsrc * B_ + b) * NDCH + d) * NB + n];
        float hv = (float)cnt * inv_n;
        float coef = 0.f;
        #pragma unroll
        for (int o = 0; o < HID; o++)
            coef += W_hist[o * NB + n] * W_comb[H_ + lp * HID + o];
        sum += hv * coef;
    }
    if (tid == 0) {
        float cst = b_comb[0];
        for (int lp = 0; lp < NALL; lp++)
            #pragma unroll
            for (int o = 0; o < HID; o++)
                cst += b_hist[o] * W_comb[H_ + lp * HID + o];
        sum += cst;
    }

    red[tid] = sum;
    __syncthreads();
    for (int s = 128; s > 0; s >>= 1) {
        if (tid < s) red[tid] += red[tid + s];
        __syncthreads();
    }
    if (tid == 0) out[b] = red[0];
}

extern "C" void kernel_launch(void* const* d_in, const int* in_sizes, int n_in,
                              void* d_out, int out_size) {
    const float* hs     = (const float*)d_in[0];
    const float* W_hist = (const float*)d_in[1];
    const float* b_hist = (const float*)d_in[2];
    const float* W_comb = (const float*)d_in[3];
    const float* b_comb = (const float*)d_in[4];
    float* out = (float*)d_out;

    // 4 launches/iter so ncu's "-s 5" (5 mod 4 == 1) lands on simhist_kernel.
    nop_kernel<<<1, 32>>>();
    dim3 grid(NDCH, B_, L_);
    simhist_kernel<<<grid, THR>>>(hs);
    final_kernel<<<B_, 256>>>(hs, W_hist, b_hist, W_comb, b_comb, out);
    nop_kernel<<<1, 32>>>();
}

// round 5
// speedup vs baseline: 2.3274x; 2.1159x over previous
#include <cuda_runtime.h>
#include <cuda_bf16.h>
#include <math.h>
#include <stdint.h>

#define L_    13
#define B_    16
#define S_    512
#define H_    768
#define QL    20
#define DL    492
#define NB    11
#define HID   5
#define NALL  14
#define KC    64            // K floats per chunk
#define NCH   12            // 768 / 64
#define NDCH  4
#define EPSF  1e-8f
#define THR   256
#define NWORK (L_ * B_ * NDCH)   // 832

__device__ int g_hist[L_ * B_ * NDCH * NB];
__device__ int g_arrive = 0;

// smem layout (bytes); base 1024-aligned so SW128 swizzle pattern is exact
#define SM_A  0              // A tile: 32 rows x 128B (bf16)
#define SM_B  4096           // B tile: 128 rows x 128B
#define SM_DN 20480          // 128 floats
#define SM_QN 20992          // 20 floats
#define SM_HI 21072          // 11 ints
#define SM_SZ 21120

#define SWZ(x) ((x) ^ (((x) >> 3) & 0x70))

__device__ __forceinline__ uint32_t sm_u32(const void* p) {
    uint32_t a;
    asm("{.reg .u64 t; cvta.to.shared.u64 t, %1; cvt.u32.u64 %0, t;}"
        : "=r"(a) : "l"(p));
    return a;
}
// pack two fp32 -> bf16x2 (lo in low half)
__device__ __forceinline__ uint32_t bfpack(float lo, float hi) {
    uint32_t r;
    asm("cvt.rn.bf16x2.f32 %0, %1, %2;" : "=r"(r) : "f"(hi), "f"(lo));
    return r;
}
__device__ __forceinline__ void ldmat4(uint32_t& r0, uint32_t& r1,
                                       uint32_t& r2, uint32_t& r3, uint32_t a) {
    asm volatile("ldmatrix.sync.aligned.m8n8.x4.shared.b16 {%0,%1,%2,%3}, [%4];"
                 : "=r"(r0), "=r"(r1), "=r"(r2), "=r"(r3) : "r"(a));
}
__device__ __forceinline__ void mma16816(float* c, uint32_t a0, uint32_t a1,
                                         uint32_t a2, uint32_t a3,
                                         uint32_t b0, uint32_t b1) {
    asm volatile(
        "mma.sync.aligned.m16n8k16.row.col.f32.bf16.bf16.f32 "
        "{%0,%1,%2,%3}, {%4,%5,%6,%7}, {%8,%9}, {%0,%1,%2,%3};"
        : "+f"(c[0]), "+f"(c[1]), "+f"(c[2]), "+f"(c[3])
        : "r"(a0), "r"(a1), "r"(a2), "r"(a3), "r"(b0), "r"(b1));
}

__global__ __launch_bounds__(THR, 2)
void cedr_fused_kernel(const float* __restrict__ hs,
                       const float* __restrict__ W_hist,
                       const float* __restrict__ b_hist,
                       const float* __restrict__ W_comb,
                       const float* __restrict__ b_comb,
                       float* __restrict__ out) {
    __shared__ __align__(1024) char sm[SM_SZ];
    const int tid  = threadIdx.x;
    const int lane = tid & 31;
    const int wid  = tid >> 5;

    // ======================= FINALIZER CTA =======================
    if (blockIdx.x == NWORK) {
        if (tid == 0) {
            while (atomicCAS(&g_arrive, NWORK, 0) != NWORK) {}
            __threadfence();
        }
        __syncthreads();
        const float inv_n = 1.0f / (float)(QL * DL);
        for (int b = wid; b < B_; b += 8) {
            float sum = 0.f;
            const float* cls = hs + (size_t)(12 * B_ + b) * S_ * H_;
            for (int h = lane; h < H_; h += 32) sum += cls[h] * W_comb[h];
            for (int i = lane; i < NALL * NB; i += 32) {
                int lp = i / NB, n = i % NB;
                int lsrc = (lp == 0) ? 0 : lp - 1;
                int cnt = 0;
                #pragma unroll
                for (int d = 0; d < NDCH; d++)
                    cnt += g_hist[((lsrc * B_ + b) * NDCH + d) * NB + n];
                float coef = 0.f;
                #pragma unroll
                for (int o = 0; o < HID; o++)
                    coef += W_hist[o * NB + n] * W_comb[H_ + lp * HID + o];
                sum += (float)cnt * inv_n * coef;
            }
            if (lane == 0) {
                float cst = b_comb[0];
                for (int lp = 0; lp < NALL; lp++)
                    #pragma unroll
                    for (int o = 0; o < HID; o++)
                        cst += b_hist[o] * W_comb[H_ + lp * HID + o];
                sum += cst;
            }
            #pragma unroll
            for (int o = 16; o > 0; o >>= 1)
                sum += __shfl_xor_sync(0xffffffffu, sum, o);
            if (lane == 0) out[b] = sum;
        }
        return;
    }

    // ======================= WORKER CTA =======================
    const int id = blockIdx.x;
    const int dc = id & 3, b = (id >> 2) & 15, l = id >> 6;
    const int dstart = dc * 128;
    const uint32_t smb = sm_u32(sm);
    float* sDn = reinterpret_cast<float*>(sm + SM_DN);
    float* sQn = reinterpret_cast<float*>(sm + SM_QN);
    int*   sHist = reinterpret_cast<int*>(sm + SM_HI);

    if (tid < NB) sHist[tid] = 0;

    // staging roles
    const int   r    = tid >> 1;          // D row 0..127
    const int   hh   = tid & 1;           // 32-float half
    const int   dgl  = dstart + r;
    const bool  dok  = dgl < DL;
    const float* dptr = hs + ((size_t)(l * B_ + b) * S_ + QL + dgl) * H_ + hh * 32;
    const int   qrow = tid >> 3;          // < 20 when qok
    const int   qsub = tid & 7;
    const float* qptr = hs + ((size_t)(l * B_ + b) * S_ + qrow) * H_ + qsub * 8;
    const bool  qok  = tid < QL * 8;

    // warp MMA tile coords
    const int mi = wid & 1;               // m16 tile: rows 16*mi..
    const int n0 = (wid >> 1) * 32;       // 4 n8-tiles at n0

    float acc[4][4];
    #pragma unroll
    for (int j = 0; j < 4; j++)
        #pragma unroll
        for (int k = 0; k < 4; k++) acc[j][k] = 0.f;

    float dn2 = 0.f, qn2 = 0.f;
    float4 dv[8], qv0, qv1;

    auto ldg_chunk = [&](int c) {
        if (dok) {
            #pragma unroll
            for (int j = 0; j < 8; j++)
                dv[j] = *reinterpret_cast<const float4*>(dptr + c * KC + j * 4);
        }
        if (qok) {
            qv0 = *reinterpret_cast<const float4*>(qptr + c * KC);
            qv1 = *reinterpret_cast<const float4*>(qptr + c * KC + 4);
        }
    };
    ldg_chunk(0);

    // ldmatrix lane geometry (shared by A and B)
    const int mm = lane >> 3, lr = lane & 7;

    for (int c = 0; c < NCH; c++) {
        // norms from current regs
        if (dok) {
            #pragma unroll
            for (int j = 0; j < 8; j++)
                dn2 += dv[j].x * dv[j].x + dv[j].y * dv[j].y
                     + dv[j].z * dv[j].z + dv[j].w * dv[j].w;
        }
        if (qok)
            qn2 += qv0.x * qv0.x + qv0.y * qv0.y + qv0.z * qv0.z + qv0.w * qv0.w
                 + qv1.x * qv1.x + qv1.y * qv1.y + qv1.z * qv1.z + qv1.w * qv1.w;

        // STS bf16, SW128
        if (dok) {
            #pragma unroll
            for (int s = 0; s < 4; s++) {
                uint4 pk;
                pk.x = bfpack(dv[2 * s].x,     dv[2 * s].y);
                pk.y = bfpack(dv[2 * s].z,     dv[2 * s].w);
                pk.z = bfpack(dv[2 * s + 1].x, dv[2 * s + 1].y);
                pk.w = bfpack(dv[2 * s + 1].z, dv[2 * s + 1].w);
                *reinterpret_cast<uint4*>(sm + SM_B + SWZ(r * 128 + hh * 64 + s * 16)) = pk;
            }
        }
        if (qok) {
            uint4 pk;
            pk.x = bfpack(qv0.x, qv0.y);
            pk.y = bfpack(qv0.z, qv0.w);
            pk.z = bfpack(qv1.x, qv1.y);
            pk.w = bfpack(qv1.z, qv1.w);
            *reinterpret_cast<uint4*>(sm + SM_A + SWZ(qrow * 128 + qsub * 16)) = pk;
        }
        __syncthreads();

        if (c + 1 < NCH) ldg_chunk(c + 1);   // overlaps MMA below

        #pragma unroll
        for (int kk = 0; kk < 4; kk++) {
            const int kb = kk * 32;
            // A m16k16: mats (row+0,k0)(row+8,k0)(row+0,k16)(row+8,k16)
            uint32_t a0, a1, a2, a3;
            {
                int arow = 16 * mi + ((mm & 1) << 3) + lr;
                int akb  = kb + ((mm >> 1) << 4);
                ldmat4(a0, a1, a2, a3, smb + SM_A + SWZ(arow * 128 + akb));
            }
            // B: two ldmatrix.x4, each covers two n8 tiles
            uint32_t br[8];
            #pragma unroll
            for (int p = 0; p < 2; p++) {
                int brow = n0 + 16 * p + ((mm >> 1) << 3) + lr;
                int bkb  = kb + ((mm & 1) << 4);
                ldmat4(br[4 * p], br[4 * p + 1], br[4 * p + 2], br[4 * p + 3],
                       smb + SM_B + SWZ(brow * 128 + bkb));
            }
            #pragma unroll
            for (int j = 0; j < 4; j++)
                mma16816(acc[j], a0, a1, a2, a3, br[2 * j], br[2 * j + 1]);
        }
        __syncthreads();
    }

    // ---- norms -> smem ----
    {
        float v = dn2 + __shfl_xor_sync(0xffffffffu, dn2, 1);
        if (hh == 0 && dok) sDn[r] = sqrtf(v);
        float q = qn2;
        q += __shfl_xor_sync(0xffffffffu, q, 1);
        q += __shfl_xor_sync(0xffffffffu, q, 2);
        q += __shfl_xor_sync(0xffffffffu, q, 4);
        if (qok && qsub == 0) sQn[qrow] = sqrtf(q);
    }
    __syncthreads();

    // ---- epilogue: cosine -> bin -> warp-aggregated histogram ----
    {
        const int lr4 = lane >> 2, lc = (lane & 3) * 2;
        const int row0 = 16 * mi + lr4, row1 = row0 + 8;
        const float qn0 = (row0 < QL) ? sQn[row0] : 1.f;
        const float qn1 = (row1 < QL) ? sQn[row1] : 1.f;
        #pragma unroll
        for (int j = 0; j < 4; j++) {
            const int col = n0 + 8 * j + lc;
            const float dn0 = sDn[col], dn1 = sDn[col + 1];
            #pragma unroll
            for (int e = 0; e < 4; e++) {
                const int rw  = (e < 2) ? row0 : row1;
                const float qn = (e < 2) ? qn0 : qn1;
                const int cl  = col + (e & 1);
                const float dn = (e & 1) ? dn1 : dn0;
                int idx = -1;
                if (rw < QL && dstart + cl < DL) {
                    float sim = acc[j][e] / fmaxf(qn * dn, EPSF);
                    float t = (sim + 1.0f) * 5.5f;
                    int bi = (int)floorf(t);
                    if (bi >= 0 && bi < NB) idx = bi;
                }
                unsigned m = __match_any_sync(0xffffffffu, idx);
                if (idx >= 0 && lane == (__ffs(m) - 1))
                    atomicAdd(&sHist[idx], __popc(m));
            }
        }
    }
    __syncthreads();
    if (tid < NB)
        g_hist[((l * B_ + b) * NDCH + dc) * NB + tid] = sHist[tid];
    __threadfence();
    __syncthreads();
    if (tid == 0) atomicAdd(&g_arrive, 1);
}

extern "C" void kernel_launch(void* const* d_in, const int* in_sizes, int n_in,
                              void* d_out, int out_size) {
    const float* hs     = (const float*)d_in[0];
    const float* W_hist = (const float*)d_in[1];
    const float* b_hist = (const float*)d_in[2];
    const float* W_comb = (const float*)d_in[3];
    const float* b_comb = (const float*)d_in[4];
    float* out = (float*)d_out;

    cedr_fused_kernel<<<NWORK + 1, THR>>>(hs, W_hist, b_hist, W_comb, b_comb, out);
}

// round 6
// speedup vs baseline: 2.3432x; 1.0068x over previous
#include <cuda_runtime.h>
#include <cuda_bf16.h>
#include <math.h>
#include <stdint.h>

#define L_    13
#define B_    16
#define S_    512
#define H_    768
#define QL    20
#define DL    492
#define NB    11
#define HID   5
#define NALL  14
#define KC    64            // K floats per chunk
#define NCH   12            // 768 / 64
#define NDCH  4
#define EPSF  1e-8f
#define THR   256
#define NWORK (L_ * B_ * NDCH)   // 832

__device__ int g_hist[L_ * B_ * NDCH * NB];
__device__ int g_arrive = 0;

// smem layout (bytes); 1024-aligned base so SW128 swizzle is exact.
// Double-buffered A (32x128B) and B (128x128B) tiles.
#define SM_A0 0
#define SM_A1 4096
#define SM_B0 8192
#define SM_B1 24576
#define SM_DN 40960          // 128 floats
#define SM_QN 41472          // 20 floats
#define SM_HI 41552          // 11 ints
#define SM_SZ 41600

#define SWZ(x) ((x) ^ (((x) >> 3) & 0x70))

__device__ __forceinline__ uint32_t sm_u32(const void* p) {
    uint32_t a;
    asm("{.reg .u64 t; cvta.to.shared.u64 t, %1; cvt.u32.u64 %0, t;}"
        : "=r"(a) : "l"(p));
    return a;
}
__device__ __forceinline__ uint32_t bfpack(float lo, float hi) {
    uint32_t r;
    asm("cvt.rn.bf16x2.f32 %0, %1, %2;" : "=r"(r) : "f"(hi), "f"(lo));
    return r;
}
__device__ __forceinline__ void ldmat4(uint32_t& r0, uint32_t& r1,
                                       uint32_t& r2, uint32_t& r3, uint32_t a) {
    asm volatile("ldmatrix.sync.aligned.m8n8.x4.shared.b16 {%0,%1,%2,%3}, [%4];"
                 : "=r"(r0), "=r"(r1), "=r"(r2), "=r"(r3) : "r"(a));
}
__device__ __forceinline__ void mma16816(float* c, uint32_t a0, uint32_t a1,
                                         uint32_t a2, uint32_t a3,
                                         uint32_t b0, uint32_t b1) {
    asm volatile(
        "mma.sync.aligned.m16n8k16.row.col.f32.bf16.bf16.f32 "
        "{%0,%1,%2,%3}, {%4,%5,%6,%7}, {%8,%9}, {%0,%1,%2,%3};"
        : "+f"(c[0]), "+f"(c[1]), "+f"(c[2]), "+f"(c[3])
        : "r"(a0), "r"(a1), "r"(a2), "r"(a3), "r"(b0), "r"(b1));
}

__global__ __launch_bounds__(THR, 2)
void cedr_fused_kernel(const float* __restrict__ hs,
                       const float* __restrict__ W_hist,
                       const float* __restrict__ b_hist,
                       const float* __restrict__ W_comb,
                       const float* __restrict__ b_comb,
                       float* __restrict__ out) {
    __shared__ __align__(1024) char sm[SM_SZ];
    const int tid  = threadIdx.x;
    const int lane = tid & 31;
    const int wid  = tid >> 5;

    // ======================= FINALIZER CTA =======================
    if (blockIdx.x == NWORK) {
        if (tid == 0) {
            while (atomicCAS(&g_arrive, NWORK, 0) != NWORK) {}
            __threadfence();
        }
        __syncthreads();
        const float inv_n = 1.0f / (float)(QL * DL);
        for (int b = wid; b < B_; b += 8) {
            float sum = 0.f;
            const float* cls = hs + (size_t)(12 * B_ + b) * S_ * H_;
            for (int h = lane; h < H_; h += 32) sum += cls[h] * W_comb[h];
            for (int i = lane; i < NALL * NB; i += 32) {
                int lp = i / NB, n = i % NB;
                int lsrc = (lp == 0) ? 0 : lp - 1;
                int cnt = 0;
                #pragma unroll
                for (int d = 0; d < NDCH; d++)
                    cnt += g_hist[((lsrc * B_ + b) * NDCH + d) * NB + n];
                float coef = 0.f;
                #pragma unroll
                for (int o = 0; o < HID; o++)
                    coef += W_hist[o * NB + n] * W_comb[H_ + lp * HID + o];
                sum += (float)cnt * inv_n * coef;
            }
            if (lane == 0) {
                float cst = b_comb[0];
                for (int lp = 0; lp < NALL; lp++)
                    #pragma unroll
                    for (int o = 0; o < HID; o++)
                        cst += b_hist[o] * W_comb[H_ + lp * HID + o];
                sum += cst;
            }
            #pragma unroll
            for (int o = 16; o > 0; o >>= 1)
                sum += __shfl_xor_sync(0xffffffffu, sum, o);
            if (lane == 0) out[b] = sum;
        }
        return;
    }

    // ======================= WORKER CTA =======================
    const int id = blockIdx.x;
    const int dc = id & 3, b = (id >> 2) & 15, l = id >> 6;
    const int dstart = dc * 128;
    const uint32_t smb = sm_u32(sm);
    float* sDn = reinterpret_cast<float*>(sm + SM_DN);
    float* sQn = reinterpret_cast<float*>(sm + SM_QN);
    int*   sHist = reinterpret_cast<int*>(sm + SM_HI);

    if (tid < NB) sHist[tid] = 0;

    // staging roles
    const int   r    = tid >> 1;          // D row 0..127
    const int   hh   = tid & 1;           // 32-float half
    const int   dgl  = dstart + r;
    const bool  dok  = dgl < DL;
    const float* dptr = hs + ((size_t)(l * B_ + b) * S_ + QL + dgl) * H_ + hh * 32;
    const int   qrow = tid >> 3;          // < 20 when qok
    const int   qsub = tid & 7;
    const float* qptr = hs + ((size_t)(l * B_ + b) * S_ + qrow) * H_ + qsub * 8;
    const bool  qok  = tid < QL * 8;

    // warp MMA tile coords
    const int mi = wid & 1;               // m16 tile
    const int n0 = (wid >> 1) * 32;       // 4 n8-tiles at n0

    float acc[4][4];
    #pragma unroll
    for (int j = 0; j < 4; j++)
        #pragma unroll
        for (int k = 0; k < 4; k++) acc[j][k] = 0.f;

    float dn2 = 0.f, qn2 = 0.f;
    float4 dv[8], qv0, qv1;

    auto ldg_chunk = [&](int c) {
        if (dok) {
            #pragma unroll
            for (int j = 0; j < 8; j++)
                dv[j] = __ldcs(reinterpret_cast<const float4*>(dptr + c * KC + j * 4));
        }
        if (qok) {
            qv0 = *reinterpret_cast<const float4*>(qptr + c * KC);
            qv1 = *reinterpret_cast<const float4*>(qptr + c * KC + 4);
        }
    };

    // norms + convert + STS of register-resident chunk into buffer bb
    auto stage_chunk = [&](int bb) {
        if (dok) {
            char* bbase = sm + (bb ? SM_B1 : SM_B0);
            #pragma unroll
            for (int j = 0; j < 8; j++)
                dn2 += dv[j].x * dv[j].x + dv[j].y * dv[j].y
                     + dv[j].z * dv[j].z + dv[j].w * dv[j].w;
            #pragma unroll
            for (int s = 0; s < 4; s++) {
                uint4 pk;
                pk.x = bfpack(dv[2 * s].x,     dv[2 * s].y);
                pk.y = bfpack(dv[2 * s].z,     dv[2 * s].w);
                pk.z = bfpack(dv[2 * s + 1].x, dv[2 * s + 1].y);
                pk.w = bfpack(dv[2 * s + 1].z, dv[2 * s + 1].w);
                *reinterpret_cast<uint4*>(bbase + SWZ(r * 128 + hh * 64 + s * 16)) = pk;
            }
        }
        if (qok) {
            char* abase = sm + (bb ? SM_A1 : SM_A0);
            qn2 += qv0.x * qv0.x + qv0.y * qv0.y + qv0.z * qv0.z + qv0.w * qv0.w
                 + qv1.x * qv1.x + qv1.y * qv1.y + qv1.z * qv1.z + qv1.w * qv1.w;
            uint4 pk;
            pk.x = bfpack(qv0.x, qv0.y);
            pk.y = bfpack(qv0.z, qv0.w);
            pk.z = bfpack(qv1.x, qv1.y);
            pk.w = bfpack(qv1.z, qv1.w);
            *reinterpret_cast<uint4*>(abase + SWZ(qrow * 128 + qsub * 16)) = pk;
        }
    };

    const int mm = lane >> 3, lr = lane & 7;   // ldmatrix lane geometry

    // prologue: stage chunk 0 into buf0
    ldg_chunk(0);
    stage_chunk(0);
    __syncthreads();

    for (int c = 0; c < NCH; c++) {
        const int s = c & 1;
        if (c + 1 < NCH) ldg_chunk(c + 1);   // in flight during MMA below

        const uint32_t abase = smb + (s ? SM_A1 : SM_A0);
        const uint32_t bbase = smb + (s ? SM_B1 : SM_B0);
        #pragma unroll
        for (int kk = 0; kk < 4; kk++) {
            const int kb = kk * 32;
            uint32_t a0, a1, a2, a3;
            {
                int arow = 16 * mi + ((mm & 1) << 3) + lr;
                int akb  = kb + ((mm >> 1) << 4);
                ldmat4(a0, a1, a2, a3, abase + SWZ(arow * 128 + akb));
            }
            uint32_t br[8];
            #pragma unroll
            for (int p = 0; p < 2; p++) {
                int brow = n0 + 16 * p + ((mm >> 1) << 3) + lr;
                int bkb  = kb + ((mm & 1) << 4);
                ldmat4(br[4 * p], br[4 * p + 1], br[4 * p + 2], br[4 * p + 3],
                       bbase + SWZ(brow * 128 + bkb));
            }
            #pragma unroll
            for (int j = 0; j < 4; j++)
                mma16816(acc[j], a0, a1, a2, a3, br[2 * j], br[2 * j + 1]);
        }

        if (c + 1 < NCH) stage_chunk(s ^ 1); // fills other buffer; no wait on MMA
        __syncthreads();                     // one barrier per chunk
    }

    // ---- norms -> smem ----
    {
        float v = dn2 + __shfl_xor_sync(0xffffffffu, dn2, 1);
        if (hh == 0 && dok) sDn[r] = sqrtf(v);
        float q = qn2;
        q += __shfl_xor_sync(0xffffffffu, q, 1);
        q += __shfl_xor_sync(0xffffffffu, q, 2);
        q += __shfl_xor_sync(0xffffffffu, q, 4);
        if (qok && qsub == 0) sQn[qrow] = sqrtf(q);
    }
    __syncthreads();

    // ---- epilogue: cosine -> bin -> warp-aggregated histogram ----
    {
        const int lr4 = lane >> 2, lc = (lane & 3) * 2;
        const int row0 = 16 * mi + lr4, row1 = row0 + 8;
        const float qn0 = (row0 < QL) ? sQn[row0] : 1.f;
        const float qn1 = (row1 < QL) ? sQn[row1] : 1.f;
        #pragma unroll
        for (int j = 0; j < 4; j++) {
            const int col = n0 + 8 * j + lc;
            const float dn0 = sDn[col], dn1 = sDn[col + 1];
            #pragma unroll
            for (int e = 0; e < 4; e++) {
                const int rw  = (e < 2) ? row0 : row1;
                const float qn = (e < 2) ? qn0 : qn1;
                const int cl  = col + (e & 1);
                const float dn = (e & 1) ? dn1 : dn0;
                int idx = -1;
                if (rw < QL && dstart + cl < DL) {
                    float sim = acc[j][e] / fmaxf(qn * dn, EPSF);
                    float t = (sim + 1.0f) * 5.5f;
                    int bi = (int)floorf(t);
                    if (bi >= 0 && bi < NB) idx = bi;
                }
                unsigned m = __match_any_sync(0xffffffffu, idx);
                if (idx >= 0 && lane == (__ffs(m) - 1))
                    atomicAdd(&sHist[idx], __popc(m));
            }
        }
    }
    __syncthreads();
    if (tid < NB)
        g_hist[((l * B_ + b) * NDCH + dc) * NB + tid] = sHist[tid];
    __threadfence();
    __syncthreads();
    if (tid == 0) atomicAdd(&g_arrive, 1);
}

extern "C" void kernel_launch(void* const* d_in, const int* in_sizes, int n_in,
                              void* d_out, int out_size) {
    const float* hs     = (const float*)d_in[0];
    const float* W_hist = (const float*)d_in[1];
    const float* b_hist = (const float*)d_in[2];
    const float* W_comb = (const float*)d_in[3];
    const float* b_comb = (const float*)d_in[4];
    float* out = (float*)d_out;

    cedr_fused_kernel<<<NWORK + 1, THR>>>(hs, W_hist, b_hist, W_comb, b_comb, out);
}

// round 7
// speedup vs baseline: 3.8612x; 1.6478x over previous
#include <cuda_runtime.h>
#include <cuda_bf16.h>
#include <math.h>
#include <stdint.h>

#define L_    13
#define B_    16
#define S_    512
#define H_    768
#define QL    20
#define DL    492
#define NB    11
#define HID   5
#define NALL  14
#define KC    64            // K floats per chunk (256B fp32, 128B bf16)
#define NCH   12            // 768 / 64
#define NDCH  4
#define EPSF  1e-8f
#define THR   256
#define NWORK (L_ * B_ * NDCH)   // 832

__device__ int g_hist[L_ * B_ * NDCH * NB];
__device__ int g_arrive = 0;

// smem layout (bytes); 1024-aligned base so SW128 swizzle is exact.
#define SM_A0 0
#define SM_A1 4096
#define SM_B0 8192
#define SM_B1 24576
#define SM_DN 40960          // 128 floats
#define SM_QN 41472          // 20 floats
#define SM_HI 41552          // 11 ints
#define SM_SZ 41600

#define SWZ(x) ((x) ^ (((x) >> 3) & 0x70))

__device__ __forceinline__ uint32_t sm_u32(const void* p) {
    uint32_t a;
    asm("{.reg .u64 t; cvta.to.shared.u64 t, %1; cvt.u32.u64 %0, t;}"
        : "=r"(a) : "l"(p));
    return a;
}
__device__ __forceinline__ uint32_t bfpack(float lo, float hi) {
    uint32_t r;
    asm("cvt.rn.bf16x2.f32 %0, %1, %2;" : "=r"(r) : "f"(hi), "f"(lo));
    return r;
}
__device__ __forceinline__ void ldmat4(uint32_t& r0, uint32_t& r1,
                                       uint32_t& r2, uint32_t& r3, uint32_t a) {
    asm volatile("ldmatrix.sync.aligned.m8n8.x4.shared.b16 {%0,%1,%2,%3}, [%4];"
                 : "=r"(r0), "=r"(r1), "=r"(r2), "=r"(r3) : "r"(a));
}
__device__ __forceinline__ void mma16816(float* c, uint32_t a0, uint32_t a1,
                                         uint32_t a2, uint32_t a3,
                                         uint32_t b0, uint32_t b1) {
    asm volatile(
        "mma.sync.aligned.m16n8k16.row.col.f32.bf16.bf16.f32 "
        "{%0,%1,%2,%3}, {%4,%5,%6,%7}, {%8,%9}, {%0,%1,%2,%3};"
        : "+f"(c[0]), "+f"(c[1]), "+f"(c[2]), "+f"(c[3])
        : "r"(a0), "r"(a1), "r"(a2), "r"(a3), "r"(b0), "r"(b1));
}

__global__ __launch_bounds__(THR, 2)
void cedr_fused_kernel(const float* __restrict__ hs,
                       const float* __restrict__ W_hist,
                       const float* __restrict__ b_hist,
                       const float* __restrict__ W_comb,
                       const float* __restrict__ b_comb,
                       float* __restrict__ out) {
    __shared__ __align__(1024) char sm[SM_SZ];
    const int tid  = threadIdx.x;
    const int lane = tid & 31;
    const int wid  = tid >> 5;

    // ======================= FINALIZER CTA =======================
    if (blockIdx.x == NWORK) {
        if (tid == 0) {
            while (atomicCAS(&g_arrive, NWORK, 0) != NWORK) {}
            __threadfence();
        }
        __syncthreads();
        const float inv_n = 1.0f / (float)(QL * DL);
        for (int b = wid; b < B_; b += 8) {
            float sum = 0.f;
            const float* cls = hs + (size_t)(12 * B_ + b) * S_ * H_;
            for (int h = lane; h < H_; h += 32) sum += cls[h] * W_comb[h];
            for (int i = lane; i < NALL * NB; i += 32) {
                int lp = i / NB, n = i % NB;
                int lsrc = (lp == 0) ? 0 : lp - 1;
                int cnt = 0;
                #pragma unroll
                for (int d = 0; d < NDCH; d++)
                    cnt += g_hist[((lsrc * B_ + b) * NDCH + d) * NB + n];
                float coef = 0.f;
                #pragma unroll
                for (int o = 0; o < HID; o++)
                    coef += W_hist[o * NB + n] * W_comb[H_ + lp * HID + o];
                sum += (float)cnt * inv_n * coef;
            }
            if (lane == 0) {
                float cst = b_comb[0];
                for (int lp = 0; lp < NALL; lp++)
                    #pragma unroll
                    for (int o = 0; o < HID; o++)
                        cst += b_hist[o] * W_comb[H_ + lp * HID + o];
                sum += cst;
            }
            #pragma unroll
            for (int o = 16; o > 0; o >>= 1)
                sum += __shfl_xor_sync(0xffffffffu, sum, o);
            if (lane == 0) out[b] = sum;
        }
        return;
    }

    // ======================= WORKER CTA =======================
    const int id = blockIdx.x;
    const int dc = id & 3, b = (id >> 2) & 15, l = id >> 6;
    const int dstart = dc * 128;
    const uint32_t smb = sm_u32(sm);
    float* sDn = reinterpret_cast<float*>(sm + SM_DN);
    float* sQn = reinterpret_cast<float*>(sm + SM_QN);
    int*   sHist = reinterpret_cast<int*>(sm + SM_HI);

    if (tid < NB) sHist[tid] = 0;

    // ---- coalesced staging roles ----
    // c16 = column (16 lanes x 16B = full 256B row chunk); lane_hi picks row.
    const int c16 = lane & 15;
    const int lane_hi = lane >> 4;
    const int rbase = wid * 16 + lane_hi * 8;     // D rows rbase..rbase+7
    const float* dbase0 = hs + ((size_t)(l * B_ + b) * S_ + QL) * H_;
    const float* qbase  = hs + (size_t)(l * B_ + b) * S_ * H_;
    const int qr0 = wid * 4 + lane_hi * 2;        // Q rows (warps 0..4 only)

    // warp MMA tile coords (unchanged)
    const int mi = wid & 1;
    const int n0 = (wid >> 1) * 32;

    float acc[4][4];
    #pragma unroll
    for (int j = 0; j < 4; j++)
        #pragma unroll
        for (int k = 0; k < 4; k++) acc[j][k] = 0.f;

    float dn2p[8];
    #pragma unroll
    for (int j = 0; j < 8; j++) dn2p[j] = 0.f;
    float qn2p[2] = {0.f, 0.f};

    float4 dv[8], qv[2];

    auto ldg_chunk = [&](int c) {
        #pragma unroll
        for (int j = 0; j < 8; j++) {
            int dgl = dstart + rbase + j;
            dv[j] = (dgl < DL)
                ? __ldcs(reinterpret_cast<const float4*>(
                      dbase0 + (size_t)dgl * H_ + c * KC + c16 * 4))
                : make_float4(0.f, 0.f, 0.f, 0.f);
        }
        if (wid < 5) {
            #pragma unroll
            for (int j = 0; j < 2; j++)
                qv[j] = *reinterpret_cast<const float4*>(
                    qbase + (size_t)(qr0 + j) * H_ + c * KC + c16 * 4);
        }
    };

    auto stage_chunk = [&](int bb) {
        char* bbase = sm + (bb ? SM_B1 : SM_B0);
        #pragma unroll
        for (int j = 0; j < 8; j++) {
            dn2p[j] += dv[j].x * dv[j].x + dv[j].y * dv[j].y
                     + dv[j].z * dv[j].z + dv[j].w * dv[j].w;
            uint2 pk;
            pk.x = bfpack(dv[j].x, dv[j].y);
            pk.y = bfpack(dv[j].z, dv[j].w);
            int row = rbase + j;
            *reinterpret_cast<uint2*>(bbase + SWZ(row * 128 + c16 * 8)) = pk;
        }
        if (wid < 5) {
            char* abase = sm + (bb ? SM_A1 : SM_A0);
            #pragma unroll
            for (int j = 0; j < 2; j++) {
                qn2p[j] += qv[j].x * qv[j].x + qv[j].y * qv[j].y
                         + qv[j].z * qv[j].z + qv[j].w * qv[j].w;
                uint2 pk;
                pk.x = bfpack(qv[j].x, qv[j].y);
                pk.y = bfpack(qv[j].z, qv[j].w);
                int row = qr0 + j;
                *reinterpret_cast<uint2*>(abase + SWZ(row * 128 + c16 * 8)) = pk;
            }
        }
    };

    const int mm = lane >> 3, lr = lane & 7;   // ldmatrix lane geometry

    ldg_chunk(0);
    stage_chunk(0);
    __syncthreads();

    for (int c = 0; c < NCH; c++) {
        const int s = c & 1;
        if (c + 1 < NCH) ldg_chunk(c + 1);

        const uint32_t abase = smb + (s ? SM_A1 : SM_A0);
        const uint32_t bbase = smb + (s ? SM_B1 : SM_B0);
        #pragma unroll
        for (int kk = 0; kk < 4; kk++) {
            const int kb = kk * 32;
            uint32_t a0, a1, a2, a3;
            {
                int arow = 16 * mi + ((mm & 1) << 3) + lr;
                int akb  = kb + ((mm >> 1) << 4);
                ldmat4(a0, a1, a2, a3, abase + SWZ(arow * 128 + akb));
            }
            uint32_t br[8];
            #pragma unroll
            for (int p = 0; p < 2; p++) {
                int brow = n0 + 16 * p + ((mm >> 1) << 3) + lr;
                int bkb  = kb + ((mm & 1) << 4);
                ldmat4(br[4 * p], br[4 * p + 1], br[4 * p + 2], br[4 * p + 3],
                       bbase + SWZ(brow * 128 + bkb));
            }
            #pragma unroll
            for (int j = 0; j < 4; j++)
                mma16816(acc[j], a0, a1, a2, a3, br[2 * j], br[2 * j + 1]);
        }

        if (c + 1 < NCH) stage_chunk(s ^ 1);
        __syncthreads();
    }

    // ---- norms: reduce across 16-lane groups, write once ----
    #pragma unroll
    for (int j = 0; j < 8; j++) {
        float v = dn2p[j];
        v += __shfl_xor_sync(0xffffffffu, v, 1);
        v += __shfl_xor_sync(0xffffffffu, v, 2);
        v += __shfl_xor_sync(0xffffffffu, v, 4);
        v += __shfl_xor_sync(0xffffffffu, v, 8);
        if (c16 == 0) sDn[rbase + j] = sqrtf(v);
    }
    if (wid < 5) {
        #pragma unroll
        for (int j = 0; j < 2; j++) {
            float v = qn2p[j];
            v += __shfl_xor_sync(0xffffffffu, v, 1);
            v += __shfl_xor_sync(0xffffffffu, v, 2);
            v += __shfl_xor_sync(0xffffffffu, v, 4);
            v += __shfl_xor_sync(0xffffffffu, v, 8);
            if (c16 == 0) sQn[qr0 + j] = sqrtf(v);
        }
    }
    __syncthreads();

    // ---- epilogue: cosine -> bin -> warp-aggregated histogram ----
    {
        const int lr4 = lane >> 2, lc = (lane & 3) * 2;
        const int row0 = 16 * mi + lr4, row1 = row0 + 8;
        const float qn0 = (row0 < QL) ? sQn[row0] : 1.f;
        const float qn1 = (row1 < QL) ? sQn[row1] : 1.f;
        #pragma unroll
        for (int j = 0; j < 4; j++) {
            const int col = n0 + 8 * j + lc;
            const float dn0 = sDn[col], dn1 = sDn[col + 1];
            #pragma unroll
            for (int e = 0; e < 4; e++) {
                const int rw  = (e < 2) ? row0 : row1;
                const float qn = (e < 2) ? qn0 : qn1;
                const int cl  = col + (e & 1);
                const float dn = (e & 1) ? dn1 : dn0;
                int idx = -1;
                if (rw < QL && dstart + cl < DL) {
                    float sim = acc[j][e] / fmaxf(qn * dn, EPSF);
                    float t = (sim + 1.0f) * 5.5f;
                    int bi = (int)floorf(t);
                    if (bi >= 0 && bi < NB) idx = bi;
                }
                unsigned m = __match_any_sync(0xffffffffu, idx);
                if (idx >= 0 && lane == (__ffs(m) - 1))
                    atomicAdd(&sHist[idx], __popc(m));
            }
        }
    }
    __syncthreads();
    if (tid < NB)
        g_hist[((l * B_ + b) * NDCH + dc) * NB + tid] = sHist[tid];
    __threadfence();
    __syncthreads();
    if (tid == 0) atomicAdd(&g_arrive, 1);
}

extern "C" void kernel_launch(void* const* d_in, const int* in_sizes, int n_in,
                              void* d_out, int out_size) {
    const float* hs     = (const float*)d_in[0];
    const float* W_hist = (const float*)d_in[1];
    const float* b_hist = (const float*)d_in[2];
    const float* W_comb = (const float*)d_in[3];
    const float* b_comb = (const float*)d_in[4];
    float* out = (float*)d_out;

    cedr_fused_kernel<<<NWORK + 1, THR>>>(hs, W_hist, b_hist, W_comb, b_comb, out);
}